// round 3
// baseline (speedup 1.0000x reference)
#include <cuda_runtime.h>
#include <math.h>

// Problem constants
#define BB  4
#define SS  1024
#define DD  1024
#define HH  16
#define HDm 64
#define MM  (BB*SS)      // 4096 rows
#define DFF (4*DD)       // 4096
#define LNEPS 1e-5f

// ---------------- scratch (device globals; no allocation allowed) ----------
__device__ float g_h1 [(size_t)MM*DD];
__device__ float g_q  [(size_t)MM*DD];
__device__ float g_k  [(size_t)MM*DD];
__device__ float g_v  [(size_t)MM*DD];
__device__ float g_sc [(size_t)BB*HH*SS*SS];   // 256 MB scores
__device__ float g_ctx[(size_t)MM*DD];
__device__ float g_x2 [(size_t)MM*DD];
__device__ float g_h2 [(size_t)MM*DD];
__device__ float g_mlp[(size_t)MM*DFF];

// ---------------- LayerNorm: one block per row of 1024 ---------------------
__global__ __launch_bounds__(256) void ln_kernel(
    const float* __restrict__ x, const float* __restrict__ g,
    const float* __restrict__ b, float* __restrict__ out)
{
    int row = blockIdx.x;
    int t = threadIdx.x;
    const float* xr = x + (size_t)row * DD;

    float v[4];
    float s = 0.f;
#pragma unroll
    for (int i = 0; i < 4; i++) { v[i] = xr[t + i*256]; s += v[i]; }

    __shared__ float warpsum[8];
    __shared__ float s_mean, s_inv;
    int lane = t & 31, wid = t >> 5;
#pragma unroll
    for (int o = 16; o > 0; o >>= 1) s += __shfl_xor_sync(~0u, s, o);
    if (lane == 0) warpsum[wid] = s;
    __syncthreads();
    if (t == 0) {
        float tot = 0.f;
#pragma unroll
        for (int i = 0; i < 8; i++) tot += warpsum[i];
        s_mean = tot * (1.f/DD);
    }
    __syncthreads();
    float mean = s_mean;

    float ss = 0.f;
#pragma unroll
    for (int i = 0; i < 4; i++) { float d = v[i]-mean; ss += d*d; }
#pragma unroll
    for (int o = 16; o > 0; o >>= 1) ss += __shfl_xor_sync(~0u, ss, o);
    if (lane == 0) warpsum[wid] = ss;
    __syncthreads();
    if (t == 0) {
        float tot = 0.f;
#pragma unroll
        for (int i = 0; i < 8; i++) tot += warpsum[i];
        s_inv = rsqrtf(tot * (1.f/DD) + LNEPS);
    }
    __syncthreads();
    float inv = s_inv;

    float* orow = out + (size_t)row * DD;
#pragma unroll
    for (int i = 0; i < 4; i++) {
        int c = t + i*256;
        orow[c] = (v[i]-mean) * inv * g[c] + b[c];
    }
}

// ---------------- generic SGEMM: C = A[MxK] @ B[KxN] (+bias)(+gelu)(+res) --
// 128x128 block tile, BK=8, 256 threads, 8x8 per thread.
template<int BIAS, int RES, int GELU>
__global__ __launch_bounds__(256) void gemm128(
    const float* __restrict__ A, const float* __restrict__ B,
    const float* __restrict__ bias, const float* __restrict__ res,
    float* __restrict__ C, int M, int N, int K)
{
    __shared__ float As[8][128];   // transposed A tile: As[k][m]
    __shared__ float Bs[8][128];   // Bs[k][n]

    int tid = threadIdx.x;
    int bx = blockIdx.x, by = blockIdx.y;

    int arow = tid >> 1;           // 0..127
    int acol = (tid & 1) * 4;      // 0 or 4
    int brow = tid >> 5;           // 0..7
    int bcol = (tid & 31) * 4;     // 0..124

    const float* Ap = A + (size_t)(by*128 + arow) * K + acol;
    const float* Bp = B + (size_t)brow * N + bx*128 + bcol;

    int tx = tid & 15, ty = tid >> 4;
    float acc[8][8] = {};

    for (int kt = 0; kt < K; kt += 8) {
        float4 av = *(const float4*)(Ap + kt);
        float4 bv = *(const float4*)(Bp + (size_t)kt * N);
        As[acol+0][arow] = av.x; As[acol+1][arow] = av.y;
        As[acol+2][arow] = av.z; As[acol+3][arow] = av.w;
        *(float4*)&Bs[brow][bcol] = bv;
        __syncthreads();
#pragma unroll
        for (int k = 0; k < 8; k++) {
            float a[8], bb[8];
#pragma unroll
            for (int i = 0; i < 8; i++) a[i]  = As[k][ty*8 + i];
#pragma unroll
            for (int j = 0; j < 8; j++) bb[j] = Bs[k][tx*8 + j];
#pragma unroll
            for (int i = 0; i < 8; i++)
#pragma unroll
                for (int j = 0; j < 8; j++)
                    acc[i][j] = fmaf(a[i], bb[j], acc[i][j]);
        }
        __syncthreads();
    }

#pragma unroll
    for (int i = 0; i < 8; i++) {
        int row = by*128 + ty*8 + i;
#pragma unroll
        for (int j = 0; j < 8; j++) {
            int col = bx*128 + tx*8 + j;
            float v = acc[i][j];
            if (BIAS) v += bias[col];
            if (GELU) v = 0.5f * v * (1.f + erff(v * 0.70710678118654752f));
            if (RES)  v += res[(size_t)row * N + col];
            C[(size_t)row * N + col] = v;
        }
    }
}

// ---------------- attention scores: S[bh, q, k] = (q . k) / 8 --------------
// block computes a 64x64 tile of scores for one (b,h); K-dim = HD = 64.
__global__ __launch_bounds__(256) void scores_kernel(
    const float* __restrict__ q, const float* __restrict__ k,
    float* __restrict__ s)
{
    __shared__ float Qs[64][65];   // transposed: Qs[d][row]
    __shared__ float Ks[64][65];   // transposed: Ks[d][col]

    int bh = blockIdx.z;
    int b = bh >> 4, h = bh & 15;
    int q0 = blockIdx.y * 64, k0 = blockIdx.x * 64;
    int tid = threadIdx.x;

    const float* qb = q + ((size_t)(b*SS + q0)) * DD + h*HDm;
    const float* kb = k + ((size_t)(b*SS + k0)) * DD + h*HDm;

#pragma unroll
    for (int it = 0; it < 4; it++) {
        int slot = it*256 + tid;     // 0..1023 float4 slots
        int row = slot >> 4;         // 0..63
        int c4  = (slot & 15) * 4;   // 0..60
        float4 qv = *(const float4*)(qb + (size_t)row*DD + c4);
        Qs[c4+0][row]=qv.x; Qs[c4+1][row]=qv.y; Qs[c4+2][row]=qv.z; Qs[c4+3][row]=qv.w;
        float4 kv = *(const float4*)(kb + (size_t)row*DD + c4);
        Ks[c4+0][row]=kv.x; Ks[c4+1][row]=kv.y; Ks[c4+2][row]=kv.z; Ks[c4+3][row]=kv.w;
    }
    __syncthreads();

    int tx = tid & 15, ty = tid >> 4;
    float acc[4][4] = {};
#pragma unroll
    for (int kk = 0; kk < 64; kk++) {
        float a[4], bb[4];
#pragma unroll
        for (int i = 0; i < 4; i++) a[i]  = Qs[kk][ty*4 + i];
#pragma unroll
        for (int j = 0; j < 4; j++) bb[j] = Ks[kk][tx*4 + j];
#pragma unroll
        for (int i = 0; i < 4; i++)
#pragma unroll
            for (int j = 0; j < 4; j++)
                acc[i][j] = fmaf(a[i], bb[j], acc[i][j]);
    }

    float* sp = s + ((size_t)bh*SS + q0) * SS + k0;
#pragma unroll
    for (int i = 0; i < 4; i++)
#pragma unroll
        for (int j = 0; j < 4; j++)
            sp[(size_t)(ty*4+i)*SS + tx*4 + j] = acc[i][j] * 0.125f;
}

// ---------------- softmax over last dim (1024), warp per row ---------------
__global__ __launch_bounds__(256) void softmax_kernel(float* __restrict__ s)
{
    int row  = blockIdx.x * 8 + (threadIdx.x >> 5);
    int lane = threadIdx.x & 31;
    float* r = s + (size_t)row * SS;

    float v[32];
    float m = -1e30f;
#pragma unroll
    for (int i = 0; i < 32; i++) { v[i] = r[lane + i*32]; m = fmaxf(m, v[i]); }
#pragma unroll
    for (int o = 16; o > 0; o >>= 1) m = fmaxf(m, __shfl_xor_sync(~0u, m, o));
    float sum = 0.f;
#pragma unroll
    for (int i = 0; i < 32; i++) { v[i] = __expf(v[i] - m); sum += v[i]; }
#pragma unroll
    for (int o = 16; o > 0; o >>= 1) sum += __shfl_xor_sync(~0u, sum, o);
    float inv = 1.f / sum;
#pragma unroll
    for (int i = 0; i < 32; i++) r[lane + i*32] = v[i] * inv;
}

// ---------------- ctx[bh, q, :] = attn[bh, q, :] @ V[bh, :, :] -------------
// block computes 64 query rows x full HD=64 for one (b,h), looping over keys.
__global__ __launch_bounds__(256) void ctx_kernel(
    const float* __restrict__ s, const float* __restrict__ v,
    float* __restrict__ ctx)
{
    __shared__ float As[64][65];   // attn tile, natural: As[row][j]
    __shared__ float Vs[64][65];   // v tile, natural: Vs[j][d]

    int bh = blockIdx.z;
    int b = bh >> 4, h = bh & 15;
    int q0 = blockIdx.y * 64;
    int tid = threadIdx.x;
    int tx = tid & 15, ty = tid >> 4;

    const float* sb = s + ((size_t)bh*SS + q0) * SS;
    const float* vb = v + ((size_t)(b*SS)) * DD + h*HDm;

    float acc[4][4] = {};
    for (int jt = 0; jt < SS; jt += 64) {
#pragma unroll
        for (int it = 0; it < 4; it++) {
            int slot = it*256 + tid;
            int row = slot >> 4;
            int c4  = (slot & 15) * 4;
            float4 av = *(const float4*)(sb + (size_t)row*SS + jt + c4);
            As[row][c4+0]=av.x; As[row][c4+1]=av.y; As[row][c4+2]=av.z; As[row][c4+3]=av.w;
            float4 vv = *(const float4*)(vb + (size_t)(jt+row)*DD + c4);
            Vs[row][c4+0]=vv.x; Vs[row][c4+1]=vv.y; Vs[row][c4+2]=vv.z; Vs[row][c4+3]=vv.w;
        }
        __syncthreads();
#pragma unroll
        for (int jj = 0; jj < 64; jj++) {
            float a[4], bb[4];
#pragma unroll
            for (int i = 0; i < 4; i++) a[i]  = As[ty*4+i][jj];
#pragma unroll
            for (int j = 0; j < 4; j++) bb[j] = Vs[jj][tx*4+j];
#pragma unroll
            for (int i = 0; i < 4; i++)
#pragma unroll
                for (int j = 0; j < 4; j++)
                    acc[i][j] = fmaf(a[i], bb[j], acc[i][j]);
        }
        __syncthreads();
    }

    float* cp = ctx + ((size_t)(b*SS + q0)) * DD + h*HDm;
#pragma unroll
    for (int i = 0; i < 4; i++)
#pragma unroll
        for (int j = 0; j < 4; j++)
            cp[(size_t)(ty*4+i)*DD + tx*4 + j] = acc[i][j];
}

// ---------------- launch ---------------------------------------------------
extern "C" void kernel_launch(void* const* d_in, const int* in_sizes, int n_in,
                              void* d_out, int out_size)
{
    const float* x    = (const float*)d_in[0];
    const float* ln1g = (const float*)d_in[1];
    const float* ln1b = (const float*)d_in[2];
    const float* wq   = (const float*)d_in[3];
    const float* bq   = (const float*)d_in[4];
    const float* wk   = (const float*)d_in[5];
    const float* bk   = (const float*)d_in[6];
    const float* wv   = (const float*)d_in[7];
    const float* bv   = (const float*)d_in[8];
    const float* wo   = (const float*)d_in[9];
    const float* bo   = (const float*)d_in[10];
    const float* ln2g = (const float*)d_in[11];
    const float* ln2b = (const float*)d_in[12];
    const float* w1   = (const float*)d_in[13];
    const float* b1   = (const float*)d_in[14];
    const float* w2   = (const float*)d_in[15];
    const float* b2   = (const float*)d_in[16];
    float* out = (float*)d_out;

    float *h1, *q, *k, *v, *sc, *ctx, *x2, *h2, *mlp;
    cudaGetSymbolAddress((void**)&h1,  g_h1);
    cudaGetSymbolAddress((void**)&q,   g_q);
    cudaGetSymbolAddress((void**)&k,   g_k);
    cudaGetSymbolAddress((void**)&v,   g_v);
    cudaGetSymbolAddress((void**)&sc,  g_sc);
    cudaGetSymbolAddress((void**)&ctx, g_ctx);
    cudaGetSymbolAddress((void**)&x2,  g_x2);
    cudaGetSymbolAddress((void**)&h2,  g_h2);
    cudaGetSymbolAddress((void**)&mlp, g_mlp);

    // 1. h1 = LN(x)
    ln_kernel<<<MM, 256>>>(x, ln1g, ln1b, h1);

    // 2. Q/K/V projections (bias fused)
    dim3 g1(DD/128, MM/128);
    gemm128<1,0,0><<<g1, 256>>>(h1, wq, bq, nullptr, q, MM, DD, DD);
    gemm128<1,0,0><<<g1, 256>>>(h1, wk, bk, nullptr, k, MM, DD, DD);
    gemm128<1,0,0><<<g1, 256>>>(h1, wv, bv, nullptr, v, MM, DD, DD);

    // 3. scores = q k^T / sqrt(HD)
    dim3 gs(SS/64, SS/64, BB*HH);
    scores_kernel<<<gs, 256>>>(q, k, sc);

    // 4. softmax rows (B*H*S = 65536 rows)
    softmax_kernel<<<(BB*HH*SS)/8, 256>>>(sc);

    // 5. ctx = attn @ v
    dim3 gc(1, SS/64, BB*HH);
    ctx_kernel<<<gc, 256>>>(sc, v, ctx);

    // 6. x2 = x + ctx @ wo + bo   (bias + residual fused)
    gemm128<1,1,0><<<g1, 256>>>(ctx, wo, bo, x, x2, MM, DD, DD);

    // 7. h2 = LN(x2)
    ln_kernel<<<MM, 256>>>(x2, ln2g, ln2b, h2);

    // 8. mlp = gelu(h2 @ w1 + b1)
    dim3 g2(DFF/128, MM/128);
    gemm128<1,0,1><<<g2, 256>>>(h2, w1, b1, nullptr, mlp, MM, DFF, DD);

    // 9. out = x2 + mlp @ w2 + b2
    gemm128<1,1,0><<<g1, 256>>>(mlp, w2, b2, x2, out, MM, DD, DFF);
}

// round 8
// speedup vs baseline: 1.2354x; 1.2354x over previous
#include <cuda_runtime.h>
#include <cuda_bf16.h>
#include <math.h>
#include <stdint.h>

#define BB  4
#define SS  1024
#define DD  1024
#define HH  16
#define HDm 64
#define MM  (BB*SS)      // 4096
#define DFF (4*DD)       // 4096
#define LNEPS 1e-5f

// ---------------- fp32 scratch ---------------------------------------------
__device__ float g_h1 [(size_t)MM*DD];
__device__ float g_q  [(size_t)MM*DD];
__device__ float g_k  [(size_t)MM*DD];
__device__ float g_v  [(size_t)MM*DD];
__device__ float g_sc [(size_t)BB*HH*SS*SS];
__device__ float g_ctx[(size_t)MM*DD];
__device__ float g_x2 [(size_t)MM*DD];
__device__ float g_h2 [(size_t)MM*DD];
__device__ float g_mlp[(size_t)MM*DFF];

// ---------------- bf16 scratch (uint4 => 16B aligned) ----------------------
__device__ uint4 g_ahi [(size_t)MM*DD*2/16];
__device__ uint4 g_alo [(size_t)MM*DD*2/16];
__device__ uint4 g_mhi [(size_t)MM*DFF*2/16];
__device__ uint4 g_mlo [(size_t)MM*DFF*2/16];
__device__ uint4 g_wqth[(size_t)DD*DD*2/16];
__device__ uint4 g_wqtl[(size_t)DD*DD*2/16];
__device__ uint4 g_wkth[(size_t)DD*DD*2/16];
__device__ uint4 g_wktl[(size_t)DD*DD*2/16];
__device__ uint4 g_wvth[(size_t)DD*DD*2/16];
__device__ uint4 g_wvtl[(size_t)DD*DD*2/16];
__device__ uint4 g_woth[(size_t)DD*DD*2/16];
__device__ uint4 g_wotl[(size_t)DD*DD*2/16];
__device__ uint4 g_w1th[(size_t)DD*DFF*2/16];
__device__ uint4 g_w1tl[(size_t)DD*DFF*2/16];
__device__ uint4 g_w2th[(size_t)DFF*DD*2/16];
__device__ uint4 g_w2tl[(size_t)DFF*DD*2/16];

// ---------------- PTX helpers (sm_80+ baseline — no 'a' gating) ------------
__device__ __forceinline__ uint32_t smem_to_u32(const void* p) {
    uint32_t a;
    asm("{ .reg .u64 t; cvta.to.shared.u64 t, %1; cvt.u32.u64 %0, t; }" : "=r"(a) : "l"(p));
    return a;
}
__device__ __forceinline__ void cp16(uint32_t dst, const void* src) {
    asm volatile("cp.async.cg.shared.global [%0], [%1], 16;" :: "r"(dst), "l"(src) : "memory");
}
__device__ __forceinline__ void ldsm4(uint32_t* r, uint32_t a) {
    asm volatile("ldmatrix.sync.aligned.m8n8.x4.shared.b16 {%0,%1,%2,%3}, [%4];"
        : "=r"(r[0]), "=r"(r[1]), "=r"(r[2]), "=r"(r[3]) : "r"(a));
}
__device__ __forceinline__ void mma16816(float* d, const uint32_t* a, const uint32_t* b) {
    asm volatile("mma.sync.aligned.m16n8k16.row.col.f32.bf16.bf16.f32 "
        "{%0,%1,%2,%3}, {%4,%5,%6,%7}, {%8,%9}, {%0,%1,%2,%3};"
        : "+f"(d[0]), "+f"(d[1]), "+f"(d[2]), "+f"(d[3])
        : "r"(a[0]), "r"(a[1]), "r"(a[2]), "r"(a[3]), "r"(b[0]), "r"(b[1]));
}

// ---------------- LayerNorm -------------------------------------------------
__global__ __launch_bounds__(256) void ln_kernel(
    const float* __restrict__ x, const float* __restrict__ g,
    const float* __restrict__ b, float* __restrict__ out)
{
    int row = blockIdx.x;
    int t = threadIdx.x;
    const float* xr = x + (size_t)row * DD;
    float v[4]; float s = 0.f;
#pragma unroll
    for (int i = 0; i < 4; i++) { v[i] = xr[t + i*256]; s += v[i]; }
    __shared__ float warpsum[8];
    __shared__ float s_mean, s_inv;
    int lane = t & 31, wid = t >> 5;
#pragma unroll
    for (int o = 16; o > 0; o >>= 1) s += __shfl_xor_sync(~0u, s, o);
    if (lane == 0) warpsum[wid] = s;
    __syncthreads();
    if (t == 0) {
        float tot = 0.f;
#pragma unroll
        for (int i = 0; i < 8; i++) tot += warpsum[i];
        s_mean = tot * (1.f/DD);
    }
    __syncthreads();
    float mean = s_mean;
    float ss = 0.f;
#pragma unroll
    for (int i = 0; i < 4; i++) { float d = v[i]-mean; ss += d*d; }
#pragma unroll
    for (int o = 16; o > 0; o >>= 1) ss += __shfl_xor_sync(~0u, ss, o);
    if (lane == 0) warpsum[wid] = ss;
    __syncthreads();
    if (t == 0) {
        float tot = 0.f;
#pragma unroll
        for (int i = 0; i < 8; i++) tot += warpsum[i];
        s_inv = rsqrtf(tot * (1.f/DD) + LNEPS);
    }
    __syncthreads();
    float inv = s_inv;
    float* orow = out + (size_t)row * DD;
#pragma unroll
    for (int i = 0; i < 4; i++) {
        int c = t + i*256;
        orow[c] = (v[i]-mean) * inv * g[c] + b[c];
    }
}

// ---------------- split fp32 -> bf16 hi/lo (vectorized x4) ------------------
__global__ __launch_bounds__(256) void split4_kernel(
    const float4* __restrict__ src, uint2* __restrict__ hi, uint2* __restrict__ lo, int n4)
{
    int i = blockIdx.x * 256 + threadIdx.x;
    if (i >= n4) return;
    float4 v = src[i];
    __nv_bfloat16 h0 = __float2bfloat16_rn(v.x);
    __nv_bfloat16 h1 = __float2bfloat16_rn(v.y);
    __nv_bfloat16 h2 = __float2bfloat16_rn(v.z);
    __nv_bfloat16 h3 = __float2bfloat16_rn(v.w);
    __nv_bfloat16 l0 = __float2bfloat16_rn(v.x - __bfloat162float(h0));
    __nv_bfloat16 l1 = __float2bfloat16_rn(v.y - __bfloat162float(h1));
    __nv_bfloat16 l2 = __float2bfloat16_rn(v.z - __bfloat162float(h2));
    __nv_bfloat16 l3 = __float2bfloat16_rn(v.w - __bfloat162float(h3));
    __nv_bfloat162 hA = __halves2bfloat162(h0, h1), hB = __halves2bfloat162(h2, h3);
    __nv_bfloat162 lA = __halves2bfloat162(l0, l1), lB = __halves2bfloat162(l2, l3);
    uint2 ho, loo;
    ho.x  = *(uint32_t*)&hA; ho.y  = *(uint32_t*)&hB;
    loo.x = *(uint32_t*)&lA; loo.y = *(uint32_t*)&lB;
    hi[i] = ho; lo[i] = loo;
}

// ---------------- weight transpose+split: W[K][N] -> Wt_hi/lo [N][K] -------
__global__ __launch_bounds__(256) void transpose_split_kernel(
    const float* __restrict__ W, __nv_bfloat16* __restrict__ Thi,
    __nv_bfloat16* __restrict__ Tlo, int K, int N)
{
    __shared__ float tile[32][33];
    int n0 = blockIdx.x * 32, k0 = blockIdx.y * 32;
    int tx = threadIdx.x, ty = threadIdx.y;  // 32 x 8
#pragma unroll
    for (int r = 0; r < 4; r++)
        tile[ty + 8*r][tx] = W[(size_t)(k0 + ty + 8*r) * N + n0 + tx];
    __syncthreads();
#pragma unroll
    for (int r = 0; r < 4; r++) {
        int rr = ty + 8*r;
        float v = tile[tx][rr];
        __nv_bfloat16 h = __float2bfloat16_rn(v);
        __nv_bfloat16 l = __float2bfloat16_rn(v - __bfloat162float(h));
        size_t oi = (size_t)(n0 + rr) * K + k0 + tx;
        Thi[oi] = h; Tlo[oi] = l;
    }
}

// ---------------- warp-MMA split-bf16 GEMM ----------------------------------
// C[M,N] = A @ B^T : A [M,K] K-major bf16 hi/lo, B [N,K] K-major bf16 hi/lo.
// 128x128 CTA tile, 8 warps of 64x32, BK=64 chunks, cp.async double buffer.
// SMEM stage: 4 sub-tiles (Ahi,Alo,Bhi,Blo), 128 rows x 144B (128B data+16B pad)
#define SUBB   (128*144)            // 18432 B per sub-tile
#define STAGEB (4*SUBB)             // 73728 B per stage
#define GSMEM_BYTES (2*STAGEB)      // 147456 B

__device__ __forceinline__ void ld_chunk(uint32_t s0, int tid,
    const char* a0, const char* a1, const char* b0, const char* b1,
    size_t strb, int kc)
{
    const char* bases[4] = { a0, a1, b0, b1 };
#pragma unroll
    for (int mtx = 0; mtx < 4; mtx++) {
        const char* base = bases[mtx];
#pragma unroll
        for (int t = 0; t < 4; t++) {
            int seg = t*256 + tid;
            int r = seg >> 3, s = seg & 7;
            cp16(s0 + mtx*SUBB + r*144 + s*16,
                 base + (size_t)r * strb + (size_t)kc * 128 + s*16);
        }
    }
    asm volatile("cp.async.commit_group;" ::: "memory");
}

template<int RES, int GELU>
__global__ __launch_bounds__(256) void gemm_mma(
    const __nv_bfloat16* __restrict__ Ahi, const __nv_bfloat16* __restrict__ Alo,
    const __nv_bfloat16* __restrict__ Bhi, const __nv_bfloat16* __restrict__ Blo,
    const float* __restrict__ bias, const float* __restrict__ res,
    float* __restrict__ C, int N, int K)
{
    extern __shared__ char smem[];
    uint32_t sb = smem_to_u32(smem);
    int tid = threadIdx.x, lane = tid & 31, wid = tid >> 5;
    int m0 = blockIdx.y * 128, n0 = blockIdx.x * 128;
    int wr = wid >> 2, wc = wid & 3;       // warp tile: rows wr*64, cols wc*32

    size_t strb = (size_t)K * 2;
    const char* a0 = (const char*)(Ahi + (size_t)m0 * K);
    const char* a1 = (const char*)(Alo + (size_t)m0 * K);
    const char* b0 = (const char*)(Bhi + (size_t)n0 * K);
    const char* b1 = (const char*)(Blo + (size_t)n0 * K);

    float acc[4][4][4];
#pragma unroll
    for (int i = 0; i < 4; i++)
#pragma unroll
        for (int j = 0; j < 4; j++)
#pragma unroll
            for (int r = 0; r < 4; r++) acc[i][j][r] = 0.f;

    int NC = K >> 6;
    ld_chunk(sb, tid, a0, a1, b0, b1, strb, 0);

    for (int i = 0; i < NC; i++) {
        if (i + 1 < NC) {
            ld_chunk(sb + ((i+1)&1)*STAGEB, tid, a0, a1, b0, b1, strb, i + 1);
            asm volatile("cp.async.wait_group 1;" ::: "memory");
        } else {
            asm volatile("cp.async.wait_group 0;" ::: "memory");
        }
        __syncthreads();

        uint32_t st = sb + (i&1)*STAGEB;
        // precomputed per-warp shared addresses
        uint32_t a_base = st + (wr*64 + (lane & 15))*144 + (lane >> 4)*16;
        uint32_t b_base = st + 2*SUBB +
            (wc*32 + (lane & 7) + ((lane >> 4) & 1)*8)*144 + ((lane >> 3) & 1)*16;

#pragma unroll
        for (int ks = 0; ks < 4; ks++) {
            uint32_t ah[4][4], al[4][4], bh[2][4], bl[2][4];
#pragma unroll
            for (int mi = 0; mi < 4; mi++) {
                uint32_t ad = a_base + mi*16*144 + ks*32;
                ldsm4(ah[mi], ad);
                ldsm4(al[mi], ad + SUBB);
            }
#pragma unroll
            for (int bj = 0; bj < 2; bj++) {
                uint32_t bd = b_base + bj*16*144 + ks*32;
                ldsm4(bh[bj], bd);
                ldsm4(bl[bj], bd + SUBB);
            }
#pragma unroll
            for (int mi = 0; mi < 4; mi++) {
#pragma unroll
                for (int nj = 0; nj < 4; nj++) {
                    const uint32_t* bH = &bh[nj >> 1][(nj & 1)*2];
                    const uint32_t* bL = &bl[nj >> 1][(nj & 1)*2];
                    mma16816(acc[mi][nj], ah[mi], bH);   // hi*hi
                    mma16816(acc[mi][nj], ah[mi], bL);   // hi*lo
                    mma16816(acc[mi][nj], al[mi], bH);   // lo*hi
                }
            }
        }
        __syncthreads();
    }

    // epilogue: direct global float2 stores with fused bias/gelu/residual
    float bx[4], by[4];
#pragma unroll
    for (int nj = 0; nj < 4; nj++) {
        int c = n0 + wc*32 + nj*8 + (lane & 3)*2;
        bx[nj] = bias[c]; by[nj] = bias[c+1];
    }
#pragma unroll
    for (int mi = 0; mi < 4; mi++) {
        int rbase = m0 + wr*64 + mi*16 + (lane >> 2);
#pragma unroll
        for (int half = 0; half < 2; half++) {
            int r = rbase + half*8;
#pragma unroll
            for (int nj = 0; nj < 4; nj++) {
                int c = n0 + wc*32 + nj*8 + (lane & 3)*2;
                float v0 = acc[mi][nj][half*2+0] + bx[nj];
                float v1 = acc[mi][nj][half*2+1] + by[nj];
                if (GELU) {
                    v0 = 0.5f * v0 * (1.f + erff(v0 * 0.70710678118654752f));
                    v1 = 0.5f * v1 * (1.f + erff(v1 * 0.70710678118654752f));
                }
                if (RES) {
                    float2 rv = *(const float2*)(res + (size_t)r * N + c);
                    v0 += rv.x; v1 += rv.y;
                }
                float2 o; o.x = v0; o.y = v1;
                *(float2*)(C + (size_t)r * N + c) = o;
            }
        }
    }
}

// ---------------- attention (SIMT fp32) -------------------------------------
__global__ __launch_bounds__(256) void scores_kernel(
    const float* __restrict__ q, const float* __restrict__ k, float* __restrict__ s)
{
    __shared__ float Qs[64][65];
    __shared__ float Ks[64][65];
    int bh = blockIdx.z;
    int b = bh >> 4, h = bh & 15;
    int q0 = blockIdx.y * 64, k0 = blockIdx.x * 64;
    int tid = threadIdx.x;
    const float* qb = q + ((size_t)(b*SS + q0)) * DD + h*HDm;
    const float* kb = k + ((size_t)(b*SS + k0)) * DD + h*HDm;
#pragma unroll
    for (int it = 0; it < 4; it++) {
        int slot = it*256 + tid;
        int row = slot >> 4;
        int c4  = (slot & 15) * 4;
        float4 qv = *(const float4*)(qb + (size_t)row*DD + c4);
        Qs[c4+0][row]=qv.x; Qs[c4+1][row]=qv.y; Qs[c4+2][row]=qv.z; Qs[c4+3][row]=qv.w;
        float4 kv = *(const float4*)(kb + (size_t)row*DD + c4);
        Ks[c4+0][row]=kv.x; Ks[c4+1][row]=kv.y; Ks[c4+2][row]=kv.z; Ks[c4+3][row]=kv.w;
    }
    __syncthreads();
    int tx = tid & 15, ty = tid >> 4;
    float acc[4][4] = {};
#pragma unroll
    for (int kk = 0; kk < 64; kk++) {
        float a[4], bb[4];
#pragma unroll
        for (int i = 0; i < 4; i++) a[i]  = Qs[kk][ty*4 + i];
#pragma unroll
        for (int j = 0; j < 4; j++) bb[j] = Ks[kk][tx*4 + j];
#pragma unroll
        for (int i = 0; i < 4; i++)
#pragma unroll
            for (int j = 0; j < 4; j++)
                acc[i][j] = fmaf(a[i], bb[j], acc[i][j]);
    }
    float* sp = s + ((size_t)bh*SS + q0) * SS + k0;
#pragma unroll
    for (int i = 0; i < 4; i++)
#pragma unroll
        for (int j = 0; j < 4; j++)
            sp[(size_t)(ty*4+i)*SS + tx*4 + j] = acc[i][j] * 0.125f;
}

__global__ __launch_bounds__(256) void softmax_kernel(float* __restrict__ s)
{
    int row  = blockIdx.x * 8 + (threadIdx.x >> 5);
    int lane = threadIdx.x & 31;
    float* r = s + (size_t)row * SS;
    float v[32];
    float m = -1e30f;
#pragma unroll
    for (int i = 0; i < 32; i++) { v[i] = r[lane + i*32]; m = fmaxf(m, v[i]); }
#pragma unroll
    for (int o = 16; o > 0; o >>= 1) m = fmaxf(m, __shfl_xor_sync(~0u, m, o));
    float sum = 0.f;
#pragma unroll
    for (int i = 0; i < 32; i++) { v[i] = __expf(v[i] - m); sum += v[i]; }
#pragma unroll
    for (int o = 16; o > 0; o >>= 1) sum += __shfl_xor_sync(~0u, sum, o);
    float inv = 1.f / sum;
#pragma unroll
    for (int i = 0; i < 32; i++) r[lane + i*32] = v[i] * inv;
}

__global__ __launch_bounds__(256) void ctx_kernel(
    const float* __restrict__ s, const float* __restrict__ v, float* __restrict__ ctx)
{
    __shared__ float As[64][65];
    __shared__ float Vs[64][65];
    int bh = blockIdx.z;
    int b = bh >> 4, h = bh & 15;
    int q0 = blockIdx.y * 64;
    int tid = threadIdx.x;
    int tx = tid & 15, ty = tid >> 4;
    const float* sb = s + ((size_t)bh*SS + q0) * SS;
    const float* vb = v + ((size_t)(b*SS)) * DD + h*HDm;
    float acc[4][4] = {};
    for (int jt = 0; jt < SS; jt += 64) {
#pragma unroll
        for (int it = 0; it < 4; it++) {
            int slot = it*256 + tid;
            int row = slot >> 4;
            int c4  = (slot & 15) * 4;
            float4 av = *(const float4*)(sb + (size_t)row*SS + jt + c4);
            As[row][c4+0]=av.x; As[row][c4+1]=av.y; As[row][c4+2]=av.z; As[row][c4+3]=av.w;
            float4 vv = *(const float4*)(vb + (size_t)(jt+row)*DD + c4);
            Vs[row][c4+0]=vv.x; Vs[row][c4+1]=vv.y; Vs[row][c4+2]=vv.z; Vs[row][c4+3]=vv.w;
        }
        __syncthreads();
#pragma unroll
        for (int jj = 0; jj < 64; jj++) {
            float a[4], bb[4];
#pragma unroll
            for (int i = 0; i < 4; i++) a[i]  = As[ty*4+i][jj];
#pragma unroll
            for (int j = 0; j < 4; j++) bb[j] = Vs[jj][tx*4+j];
#pragma unroll
            for (int i = 0; i < 4; i++)
#pragma unroll
                for (int j = 0; j < 4; j++)
                    acc[i][j] = fmaf(a[i], bb[j], acc[i][j]);
        }
        __syncthreads();
    }
    float* cp = ctx + ((size_t)(b*SS + q0)) * DD + h*HDm;
#pragma unroll
    for (int i = 0; i < 4; i++)
#pragma unroll
        for (int j = 0; j < 4; j++)
            cp[(size_t)(ty*4+i)*DD + tx*4 + j] = acc[i][j];
}

// ---------------- launch ----------------------------------------------------
extern "C" void kernel_launch(void* const* d_in, const int* in_sizes, int n_in,
                              void* d_out, int out_size)
{
    const float* x    = (const float*)d_in[0];
    const float* ln1g = (const float*)d_in[1];
    const float* ln1b = (const float*)d_in[2];
    const float* wq   = (const float*)d_in[3];
    const float* bq   = (const float*)d_in[4];
    const float* wk   = (const float*)d_in[5];
    const float* bk   = (const float*)d_in[6];
    const float* wv   = (const float*)d_in[7];
    const float* bv   = (const float*)d_in[8];
    const float* wo   = (const float*)d_in[9];
    const float* bo   = (const float*)d_in[10];
    const float* ln2g = (const float*)d_in[11];
    const float* ln2b = (const float*)d_in[12];
    const float* w1   = (const float*)d_in[13];
    const float* b1   = (const float*)d_in[14];
    const float* w2   = (const float*)d_in[15];
    const float* b2   = (const float*)d_in[16];
    float* out = (float*)d_out;

    float *h1, *q, *k, *v, *sc, *ctx, *x2, *h2, *mlp;
    cudaGetSymbolAddress((void**)&h1,  g_h1);
    cudaGetSymbolAddress((void**)&q,   g_q);
    cudaGetSymbolAddress((void**)&k,   g_k);
    cudaGetSymbolAddress((void**)&v,   g_v);
    cudaGetSymbolAddress((void**)&sc,  g_sc);
    cudaGetSymbolAddress((void**)&ctx, g_ctx);
    cudaGetSymbolAddress((void**)&x2,  g_x2);
    cudaGetSymbolAddress((void**)&h2,  g_h2);
    cudaGetSymbolAddress((void**)&mlp, g_mlp);

    __nv_bfloat16 *ahi, *alo, *mhi, *mlo;
    __nv_bfloat16 *wqth, *wqtl, *wkth, *wktl, *wvth, *wvtl, *woth, *wotl;
    __nv_bfloat16 *w1th, *w1tl, *w2th, *w2tl;
    cudaGetSymbolAddress((void**)&ahi,  g_ahi);
    cudaGetSymbolAddress((void**)&alo,  g_alo);
    cudaGetSymbolAddress((void**)&mhi,  g_mhi);
    cudaGetSymbolAddress((void**)&mlo,  g_mlo);
    cudaGetSymbolAddress((void**)&wqth, g_wqth);
    cudaGetSymbolAddress((void**)&wqtl, g_wqtl);
    cudaGetSymbolAddress((void**)&wkth, g_wkth);
    cudaGetSymbolAddress((void**)&wktl, g_wktl);
    cudaGetSymbolAddress((void**)&wvth, g_wvth);
    cudaGetSymbolAddress((void**)&wvtl, g_wvtl);
    cudaGetSymbolAddress((void**)&woth, g_woth);
    cudaGetSymbolAddress((void**)&wotl, g_wotl);
    cudaGetSymbolAddress((void**)&w1th, g_w1th);
    cudaGetSymbolAddress((void**)&w1tl, g_w1tl);
    cudaGetSymbolAddress((void**)&w2th, g_w2th);
    cudaGetSymbolAddress((void**)&w2tl, g_w2tl);

    cudaFuncSetAttribute(gemm_mma<0,0>, cudaFuncAttributeMaxDynamicSharedMemorySize, GSMEM_BYTES);
    cudaFuncSetAttribute(gemm_mma<1,0>, cudaFuncAttributeMaxDynamicSharedMemorySize, GSMEM_BYTES);
    cudaFuncSetAttribute(gemm_mma<0,1>, cudaFuncAttributeMaxDynamicSharedMemorySize, GSMEM_BYTES);

    dim3 tb(32, 8);

    // weight transpose+split (one-shot per launch)
    transpose_split_kernel<<<dim3(DD/32,  DD/32),  tb>>>(wq, wqth, wqtl, DD,  DD);
    transpose_split_kernel<<<dim3(DD/32,  DD/32),  tb>>>(wk, wkth, wktl, DD,  DD);
    transpose_split_kernel<<<dim3(DD/32,  DD/32),  tb>>>(wv, wvth, wvtl, DD,  DD);
    transpose_split_kernel<<<dim3(DD/32,  DD/32),  tb>>>(wo, woth, wotl, DD,  DD);
    transpose_split_kernel<<<dim3(DFF/32, DD/32),  tb>>>(w1, w1th, w1tl, DD,  DFF);
    transpose_split_kernel<<<dim3(DD/32,  DFF/32), tb>>>(w2, w2th, w2tl, DFF, DD);

    // 1. h1 = LN(x); split
    ln_kernel<<<MM, 256>>>(x, ln1g, ln1b, h1);
    split4_kernel<<<(MM*DD/4)/256, 256>>>((const float4*)h1, (uint2*)ahi, (uint2*)alo, MM*DD/4);

    // 2. Q/K/V projections (warp MMA)
    dim3 g1(DD/128, MM/128);
    gemm_mma<0,0><<<g1, 256, GSMEM_BYTES>>>(ahi, alo, wqth, wqtl, bq, nullptr, q, DD, DD);
    gemm_mma<0,0><<<g1, 256, GSMEM_BYTES>>>(ahi, alo, wkth, wktl, bk, nullptr, k, DD, DD);
    gemm_mma<0,0><<<g1, 256, GSMEM_BYTES>>>(ahi, alo, wvth, wvtl, bv, nullptr, v, DD, DD);

    // 3-5. attention
    dim3 gs(SS/64, SS/64, BB*HH);
    scores_kernel<<<gs, 256>>>(q, k, sc);
    softmax_kernel<<<(BB*HH*SS)/8, 256>>>(sc);
    dim3 gc(1, SS/64, BB*HH);
    ctx_kernel<<<gc, 256>>>(sc, v, ctx);

    // 6. x2 = x + ctx @ wo + bo
    split4_kernel<<<(MM*DD/4)/256, 256>>>((const float4*)ctx, (uint2*)ahi, (uint2*)alo, MM*DD/4);
    gemm_mma<1,0><<<g1, 256, GSMEM_BYTES>>>(ahi, alo, woth, wotl, bo, x, x2, DD, DD);

    // 7. h2 = LN(x2); split
    ln_kernel<<<MM, 256>>>(x2, ln2g, ln2b, h2);
    split4_kernel<<<(MM*DD/4)/256, 256>>>((const float4*)h2, (uint2*)ahi, (uint2*)alo, MM*DD/4);

    // 8. mlp = gelu(h2 @ w1 + b1)
    dim3 g2(DFF/128, MM/128);
    gemm_mma<0,1><<<g2, 256, GSMEM_BYTES>>>(ahi, alo, w1th, w1tl, b1, nullptr, mlp, DFF, DD);

    // 9. out = x2 + mlp @ w2 + b2
    split4_kernel<<<(MM*DFF/4)/256, 256>>>((const float4*)mlp, (uint2*)mhi, (uint2*)mlo, MM*DFF/4);
    gemm_mma<1,0><<<g1, 256, GSMEM_BYTES>>>(mhi, mlo, w2th, w2tl, b2, x2, out, DD, DFF);
}

// round 9
// speedup vs baseline: 2.8878x; 2.3376x over previous
#include <cuda_runtime.h>
#include <cuda_bf16.h>
#include <math.h>
#include <stdint.h>

#define BB  4
#define SS  1024
#define DD  1024
#define HH  16
#define HDm 64
#define MM  (BB*SS)      // 4096
#define DFF (4*DD)       // 4096
#define LNEPS 1e-5f

// ---------------- scratch ----------------------------------------------------
__device__ float g_x2 [(size_t)MM*DD];

// bf16 hi/lo buffers (uint4 => 16B aligned)
__device__ uint4 g_ahi [(size_t)MM*DD*2/16];   // h1 -> later ctx
__device__ uint4 g_alo [(size_t)MM*DD*2/16];
__device__ uint4 g_qhi [(size_t)MM*DD*2/16];   // q -> later h2
__device__ uint4 g_qlo [(size_t)MM*DD*2/16];
__device__ uint4 g_khi [(size_t)MM*DD*2/16];
__device__ uint4 g_klo [(size_t)MM*DD*2/16];
__device__ uint4 g_vhi [(size_t)MM*DD*2/16];
__device__ uint4 g_vlo [(size_t)MM*DD*2/16];
__device__ uint4 g_mhi [(size_t)MM*DFF*2/16];
__device__ uint4 g_mlo [(size_t)MM*DFF*2/16];
__device__ uint4 g_wqth[(size_t)DD*DD*2/16];
__device__ uint4 g_wqtl[(size_t)DD*DD*2/16];
__device__ uint4 g_wkth[(size_t)DD*DD*2/16];
__device__ uint4 g_wktl[(size_t)DD*DD*2/16];
__device__ uint4 g_wvth[(size_t)DD*DD*2/16];
__device__ uint4 g_wvtl[(size_t)DD*DD*2/16];
__device__ uint4 g_woth[(size_t)DD*DD*2/16];
__device__ uint4 g_wotl[(size_t)DD*DD*2/16];
__device__ uint4 g_w1th[(size_t)DD*DFF*2/16];
__device__ uint4 g_w1tl[(size_t)DD*DFF*2/16];
__device__ uint4 g_w2th[(size_t)DFF*DD*2/16];
__device__ uint4 g_w2tl[(size_t)DFF*DD*2/16];

// ---------------- PTX helpers (sm_80+ baseline) ------------------------------
__device__ __forceinline__ uint32_t smem_to_u32(const void* p) {
    uint32_t a;
    asm("{ .reg .u64 t; cvta.to.shared.u64 t, %1; cvt.u32.u64 %0, t; }" : "=r"(a) : "l"(p));
    return a;
}
__device__ __forceinline__ void cp16(uint32_t dst, const void* src) {
    asm volatile("cp.async.cg.shared.global [%0], [%1], 16;" :: "r"(dst), "l"(src) : "memory");
}
__device__ __forceinline__ void ldsm4(uint32_t* r, uint32_t a) {
    asm volatile("ldmatrix.sync.aligned.m8n8.x4.shared.b16 {%0,%1,%2,%3}, [%4];"
        : "=r"(r[0]), "=r"(r[1]), "=r"(r[2]), "=r"(r[3]) : "r"(a));
}
__device__ __forceinline__ void ldsm4t(uint32_t* r, uint32_t a) {
    asm volatile("ldmatrix.sync.aligned.m8n8.x4.trans.shared.b16 {%0,%1,%2,%3}, [%4];"
        : "=r"(r[0]), "=r"(r[1]), "=r"(r[2]), "=r"(r[3]) : "r"(a));
}
__device__ __forceinline__ void mma16816(float* d, const uint32_t* a, const uint32_t* b) {
    asm volatile("mma.sync.aligned.m16n8k16.row.col.f32.bf16.bf16.f32 "
        "{%0,%1,%2,%3}, {%4,%5,%6,%7}, {%8,%9}, {%0,%1,%2,%3};"
        : "+f"(d[0]), "+f"(d[1]), "+f"(d[2]), "+f"(d[3])
        : "r"(a[0]), "r"(a[1]), "r"(a[2]), "r"(a[3]), "r"(b[0]), "r"(b[1]));
}
__device__ __forceinline__ void packhl(float x, float y, uint32_t& hi, uint32_t& lo) {
    __nv_bfloat16 hx = __float2bfloat16_rn(x), hy = __float2bfloat16_rn(y);
    __nv_bfloat16 lx = __float2bfloat16_rn(x - __bfloat162float(hx));
    __nv_bfloat16 ly = __float2bfloat16_rn(y - __bfloat162float(hy));
    __nv_bfloat162 h2 = __halves2bfloat162(hx, hy), l2 = __halves2bfloat162(lx, ly);
    hi = *(uint32_t*)&h2; lo = *(uint32_t*)&l2;
}

// ---------------- LayerNorm with hi/lo split output --------------------------
__global__ __launch_bounds__(256) void ln_split_kernel(
    const float* __restrict__ x, const float* __restrict__ g,
    const float* __restrict__ b,
    __nv_bfloat16* __restrict__ ohi, __nv_bfloat16* __restrict__ olo)
{
    int row = blockIdx.x;
    int t = threadIdx.x;
    const float* xr = x + (size_t)row * DD;
    float v[4]; float s = 0.f;
#pragma unroll
    for (int i = 0; i < 4; i++) { v[i] = xr[t + i*256]; s += v[i]; }
    __shared__ float warpsum[8];
    __shared__ float s_mean, s_inv;
    int lane = t & 31, wid = t >> 5;
#pragma unroll
    for (int o = 16; o > 0; o >>= 1) s += __shfl_xor_sync(~0u, s, o);
    if (lane == 0) warpsum[wid] = s;
    __syncthreads();
    if (t == 0) {
        float tot = 0.f;
#pragma unroll
        for (int i = 0; i < 8; i++) tot += warpsum[i];
        s_mean = tot * (1.f/DD);
    }
    __syncthreads();
    float mean = s_mean;
    float ss = 0.f;
#pragma unroll
    for (int i = 0; i < 4; i++) { float d = v[i]-mean; ss += d*d; }
#pragma unroll
    for (int o = 16; o > 0; o >>= 1) ss += __shfl_xor_sync(~0u, ss, o);
    if (lane == 0) warpsum[wid] = ss;
    __syncthreads();
    if (t == 0) {
        float tot = 0.f;
#pragma unroll
        for (int i = 0; i < 8; i++) tot += warpsum[i];
        s_inv = rsqrtf(tot * (1.f/DD) + LNEPS);
    }
    __syncthreads();
    float inv = s_inv;
#pragma unroll
    for (int i = 0; i < 4; i++) {
        int c = t + i*256;
        float o = (v[i]-mean) * inv * g[c] + b[c];
        __nv_bfloat16 h = __float2bfloat16_rn(o);
        __nv_bfloat16 l = __float2bfloat16_rn(o - __bfloat162float(h));
        ohi[(size_t)row*DD + c] = h;
        olo[(size_t)row*DD + c] = l;
    }
}

// ---------------- weight transpose+split: W[K][N] -> Wt_hi/lo [N][K] ---------
__global__ __launch_bounds__(256) void transpose_split_kernel(
    const float* __restrict__ W, __nv_bfloat16* __restrict__ Thi,
    __nv_bfloat16* __restrict__ Tlo, int K, int N)
{
    __shared__ float tile[32][33];
    int n0 = blockIdx.x * 32, k0 = blockIdx.y * 32;
    int tx = threadIdx.x, ty = threadIdx.y;  // 32 x 8
#pragma unroll
    for (int r = 0; r < 4; r++)
        tile[ty + 8*r][tx] = W[(size_t)(k0 + ty + 8*r) * N + n0 + tx];
    __syncthreads();
#pragma unroll
    for (int r = 0; r < 4; r++) {
        int rr = ty + 8*r;
        float v = tile[tx][rr];
        __nv_bfloat16 h = __float2bfloat16_rn(v);
        __nv_bfloat16 l = __float2bfloat16_rn(v - __bfloat162float(h));
        size_t oi = (size_t)(n0 + rr) * K + k0 + tx;
        Thi[oi] = h; Tlo[oi] = l;
    }
}

// ---------------- warp-MMA split-bf16 GEMM -----------------------------------
// C = A @ B^T : A [M,K] hi/lo, B [N,K] hi/lo. 128x128 CTA, 8 warps 64x32.
#define SUBB   (128*144)
#define STAGEB (4*SUBB)
#define GSMEM_BYTES (2*STAGEB)

__device__ __forceinline__ void ld_chunk(uint32_t s0, int tid,
    const char* a0, const char* a1, const char* b0, const char* b1,
    size_t strb, int kc)
{
    const char* bases[4] = { a0, a1, b0, b1 };
#pragma unroll
    for (int mtx = 0; mtx < 4; mtx++) {
        const char* base = bases[mtx];
#pragma unroll
        for (int t = 0; t < 4; t++) {
            int seg = t*256 + tid;
            int r = seg >> 3, s = seg & 7;
            cp16(s0 + mtx*SUBB + r*144 + s*16,
                 base + (size_t)r * strb + (size_t)kc * 128 + s*16);
        }
    }
    asm volatile("cp.async.commit_group;" ::: "memory");
}

// SPLIT: write Chi/Clo bf16 instead of C fp32. scale applied after bias.
template<int RES, int GELU, int SPLIT>
__global__ __launch_bounds__(256) void gemm_mma(
    const __nv_bfloat16* __restrict__ Ahi, const __nv_bfloat16* __restrict__ Alo,
    const __nv_bfloat16* __restrict__ Bhi, const __nv_bfloat16* __restrict__ Blo,
    const float* __restrict__ bias, const float* __restrict__ res,
    float* __restrict__ C, __nv_bfloat16* __restrict__ Chi,
    __nv_bfloat16* __restrict__ Clo, float scale, int N, int K)
{
    extern __shared__ char smem[];
    uint32_t sb = smem_to_u32(smem);
    int tid = threadIdx.x, lane = tid & 31, wid = tid >> 5;
    int m0 = blockIdx.y * 128, n0 = blockIdx.x * 128;
    int wr = wid >> 2, wc = wid & 3;

    size_t strb = (size_t)K * 2;
    const char* a0 = (const char*)(Ahi + (size_t)m0 * K);
    const char* a1 = (const char*)(Alo + (size_t)m0 * K);
    const char* b0 = (const char*)(Bhi + (size_t)n0 * K);
    const char* b1 = (const char*)(Blo + (size_t)n0 * K);

    float acc[4][4][4];
#pragma unroll
    for (int i = 0; i < 4; i++)
#pragma unroll
        for (int j = 0; j < 4; j++)
#pragma unroll
            for (int r = 0; r < 4; r++) acc[i][j][r] = 0.f;

    int NC = K >> 6;
    ld_chunk(sb, tid, a0, a1, b0, b1, strb, 0);

    for (int i = 0; i < NC; i++) {
        if (i + 1 < NC) {
            ld_chunk(sb + ((i+1)&1)*STAGEB, tid, a0, a1, b0, b1, strb, i + 1);
            asm volatile("cp.async.wait_group 1;" ::: "memory");
        } else {
            asm volatile("cp.async.wait_group 0;" ::: "memory");
        }
        __syncthreads();

        uint32_t st = sb + (i&1)*STAGEB;
        uint32_t a_base = st + (wr*64 + (lane & 15))*144 + (lane >> 4)*16;
        uint32_t b_base = st + 2*SUBB +
            (wc*32 + (lane & 7) + ((lane >> 4) & 1)*8)*144 + ((lane >> 3) & 1)*16;

#pragma unroll
        for (int ks = 0; ks < 4; ks++) {
            uint32_t ah[4][4], al[4][4], bh[2][4], bl[2][4];
#pragma unroll
            for (int mi = 0; mi < 4; mi++) {
                uint32_t ad = a_base + mi*16*144 + ks*32;
                ldsm4(ah[mi], ad);
                ldsm4(al[mi], ad + SUBB);
            }
#pragma unroll
            for (int bj = 0; bj < 2; bj++) {
                uint32_t bd = b_base + bj*16*144 + ks*32;
                ldsm4(bh[bj], bd);
                ldsm4(bl[bj], bd + SUBB);
            }
#pragma unroll
            for (int mi = 0; mi < 4; mi++) {
#pragma unroll
                for (int nj = 0; nj < 4; nj++) {
                    const uint32_t* bH = &bh[nj >> 1][(nj & 1)*2];
                    const uint32_t* bL = &bl[nj >> 1][(nj & 1)*2];
                    mma16816(acc[mi][nj], ah[mi], bH);
                    mma16816(acc[mi][nj], ah[mi], bL);
                    mma16816(acc[mi][nj], al[mi], bH);
                }
            }
        }
        __syncthreads();
    }

    float bx[4], by[4];
#pragma unroll
    for (int nj = 0; nj < 4; nj++) {
        int c = n0 + wc*32 + nj*8 + (lane & 3)*2;
        bx[nj] = bias[c]; by[nj] = bias[c+1];
    }
#pragma unroll
    for (int mi = 0; mi < 4; mi++) {
        int rbase = m0 + wr*64 + mi*16 + (lane >> 2);
#pragma unroll
        for (int half = 0; half < 2; half++) {
            int r = rbase + half*8;
#pragma unroll
            for (int nj = 0; nj < 4; nj++) {
                int c = n0 + wc*32 + nj*8 + (lane & 3)*2;
                float v0 = (acc[mi][nj][half*2+0] + bx[nj]) * scale;
                float v1 = (acc[mi][nj][half*2+1] + by[nj]) * scale;
                if (GELU) {
                    v0 = 0.5f * v0 * (1.f + erff(v0 * 0.70710678118654752f));
                    v1 = 0.5f * v1 * (1.f + erff(v1 * 0.70710678118654752f));
                }
                if (RES) {
                    float2 rv = *(const float2*)(res + (size_t)r * N + c);
                    v0 += rv.x; v1 += rv.y;
                }
                if (SPLIT) {
                    uint32_t hi, lo;
                    packhl(v0, v1, hi, lo);
                    *(uint32_t*)(Chi + (size_t)r * N + c) = hi;
                    *(uint32_t*)(Clo + (size_t)r * N + c) = lo;
                } else {
                    float2 o; o.x = v0; o.y = v1;
                    *(float2*)(C + (size_t)r * N + c) = o;
                }
            }
        }
    }
}

// ---------------- fused flash attention --------------------------------------
// grid (SS/128, BB*HH), 256 threads (8 warps x 16 q-rows).
// K/V chunks of 128 keys, online softmax, 3-pass split-bf16 MMA both stages.
#define FQH 0
#define FQL 18432
#define FKH 36864
#define FKL 55296
#define FVH 73728
#define FVL 92160
#define FSMEM 110592

__device__ __forceinline__ void fl_load_tile(uint32_t dst, int tid, const char* g)
{
#pragma unroll
    for (int t = 0; t < 4; t++) {
        int seg = t*256 + tid;
        int r = seg >> 3, s = seg & 7;
        cp16(dst + r*144 + s*16, g + (size_t)r * (DD*2) + s*16);
    }
}

__global__ __launch_bounds__(256) void flash_kernel(
    const __nv_bfloat16* __restrict__ qhi, const __nv_bfloat16* __restrict__ qlo,
    const __nv_bfloat16* __restrict__ khi, const __nv_bfloat16* __restrict__ klo,
    const __nv_bfloat16* __restrict__ vhi, const __nv_bfloat16* __restrict__ vlo,
    __nv_bfloat16* __restrict__ chi, __nv_bfloat16* __restrict__ clo)
{
    extern __shared__ char smem[];
    uint32_t sb = smem_to_u32(smem);
    int tid = threadIdx.x, lane = tid & 31, w = tid >> 5;
    int q0 = blockIdx.x * 128;
    int bh = blockIdx.y, b = bh >> 4, h = bh & 15;

    size_t qoff = ((size_t)(b*SS + q0) * DD + h*HDm) * 2;
    size_t koff = ((size_t)(b*SS) * DD + h*HDm) * 2;

    // prologue: Q tile + chunk 0
    fl_load_tile(sb + FQH, tid, (const char*)qhi + qoff);
    fl_load_tile(sb + FQL, tid, (const char*)qlo + qoff);
    fl_load_tile(sb + FKH, tid, (const char*)khi + koff);
    fl_load_tile(sb + FKL, tid, (const char*)klo + koff);
    fl_load_tile(sb + FVH, tid, (const char*)vhi + koff);
    fl_load_tile(sb + FVL, tid, (const char*)vlo + koff);
    asm volatile("cp.async.commit_group;" ::: "memory");

    float oacc[8][4];
#pragma unroll
    for (int i = 0; i < 8; i++)
#pragma unroll
        for (int r = 0; r < 4; r++) oacc[i][r] = 0.f;
    float mrow[2] = { -1e30f, -1e30f };
    float lrow[2] = { 0.f, 0.f };

    uint32_t a_base = sb + FQH + (w*16 + (lane & 15))*144 + (lane >> 4)*16;

    for (int j = 0; j < SS/128; j++) {
        asm volatile("cp.async.wait_group 0;" ::: "memory");
        __syncthreads();

        // ---- S = Q K^T (3-pass) ----
        float sacc[16][4];
#pragma unroll
        for (int i = 0; i < 16; i++)
#pragma unroll
            for (int r = 0; r < 4; r++) sacc[i][r] = 0.f;

#pragma unroll
        for (int ks = 0; ks < 4; ks++) {
            uint32_t ah[4], al[4];
            ldsm4(ah, a_base + ks*32);
            ldsm4(al, a_base + (FQL-FQH) + ks*32);
#pragma unroll
            for (int nt = 0; nt < 8; nt++) {
                uint32_t bh4[4], bl4[4];
                uint32_t bd = sb + FKH + (nt*16 + (lane & 7) + ((lane >> 4) & 1)*8)*144
                            + ((lane >> 3) & 1)*16 + ks*32;
                ldsm4(bh4, bd);
                ldsm4(bl4, bd + (FKL-FKH));
#pragma unroll
                for (int half = 0; half < 2; half++) {
                    mma16816(sacc[2*nt+half], ah, &bh4[half*2]);
                    mma16816(sacc[2*nt+half], ah, &bl4[half*2]);
                    mma16816(sacc[2*nt+half], al, &bh4[half*2]);
                }
            }
        }

        // ---- online softmax ----
#pragma unroll
        for (int half = 0; half < 2; half++) {
            float mx = -1e30f;
#pragma unroll
            for (int nt = 0; nt < 16; nt++) {
                mx = fmaxf(mx, sacc[nt][half*2+0]);
                mx = fmaxf(mx, sacc[nt][half*2+1]);
            }
            mx = fmaxf(mx, __shfl_xor_sync(~0u, mx, 1));
            mx = fmaxf(mx, __shfl_xor_sync(~0u, mx, 2));
            float mnew = fmaxf(mrow[half], mx);
            float alpha = __expf(mrow[half] - mnew);
            mrow[half] = mnew;
            float sum = 0.f;
#pragma unroll
            for (int nt = 0; nt < 16; nt++) {
                float p0 = __expf(sacc[nt][half*2+0] - mnew);
                float p1 = __expf(sacc[nt][half*2+1] - mnew);
                sacc[nt][half*2+0] = p0; sacc[nt][half*2+1] = p1;
                sum += p0 + p1;
            }
            lrow[half] = lrow[half] * alpha + sum;
#pragma unroll
            for (int on = 0; on < 8; on++) {
                oacc[on][half*2+0] *= alpha;
                oacc[on][half*2+1] *= alpha;
            }
        }

        // ---- O += P V (3-pass) ----
#pragma unroll
        for (int kt = 0; kt < 8; kt++) {
            uint32_t phi[4], plo[4];
            packhl(sacc[2*kt  ][0], sacc[2*kt  ][1], phi[0], plo[0]);
            packhl(sacc[2*kt  ][2], sacc[2*kt  ][3], phi[1], plo[1]);
            packhl(sacc[2*kt+1][0], sacc[2*kt+1][1], phi[2], plo[2]);
            packhl(sacc[2*kt+1][2], sacc[2*kt+1][3], phi[3], plo[3]);
#pragma unroll
            for (int np = 0; np < 4; np++) {
                uint32_t vh4[4], vl4[4];
                uint32_t vd = sb + FVH + (16*kt + (lane & 15))*144
                            + (np*16 + (lane >> 4)*8)*2;
                ldsm4t(vh4, vd);
                ldsm4t(vl4, vd + (FVL-FVH));
#pragma unroll
                for (int half = 0; half < 2; half++) {
                    mma16816(oacc[2*np+half], phi, &vh4[half*2]);
                    mma16816(oacc[2*np+half], phi, &vl4[half*2]);
                    mma16816(oacc[2*np+half], plo, &vh4[half*2]);
                }
            }
        }

        __syncthreads();
        if (j + 1 < SS/128) {
            size_t off = koff + (size_t)(j+1) * 128 * DD * 2;
            fl_load_tile(sb + FKH, tid, (const char*)khi + off);
            fl_load_tile(sb + FKL, tid, (const char*)klo + off);
            fl_load_tile(sb + FVH, tid, (const char*)vhi + off);
            fl_load_tile(sb + FVL, tid, (const char*)vlo + off);
            asm volatile("cp.async.commit_group;" ::: "memory");
        }
    }

    // ---- epilogue: normalize, write ctx hi/lo ----
#pragma unroll
    for (int half = 0; half < 2; half++) {
        float l = lrow[half];
        l += __shfl_xor_sync(~0u, l, 1);
        l += __shfl_xor_sync(~0u, l, 2);
        float inv = 1.f / l;
        int r = b*SS + q0 + w*16 + (lane >> 2) + half*8;
#pragma unroll
        for (int on = 0; on < 8; on++) {
            int c = h*HDm + on*8 + (lane & 3)*2;
            float v0 = oacc[on][half*2+0] * inv;
            float v1 = oacc[on][half*2+1] * inv;
            uint32_t hi, lo;
            packhl(v0, v1, hi, lo);
            *(uint32_t*)(chi + (size_t)r * DD + c) = hi;
            *(uint32_t*)(clo + (size_t)r * DD + c) = lo;
        }
    }
}

// ---------------- launch ------------------------------------------------------
extern "C" void kernel_launch(void* const* d_in, const int* in_sizes, int n_in,
                              void* d_out, int out_size)
{
    const float* x    = (const float*)d_in[0];
    const float* ln1g = (const float*)d_in[1];
    const float* ln1b = (const float*)d_in[2];
    const float* wq   = (const float*)d_in[3];
    const float* bq   = (const float*)d_in[4];
    const float* wk   = (const float*)d_in[5];
    const float* bk   = (const float*)d_in[6];
    const float* wv   = (const float*)d_in[7];
    const float* bv   = (const float*)d_in[8];
    const float* wo   = (const float*)d_in[9];
    const float* bo   = (const float*)d_in[10];
    const float* ln2g = (const float*)d_in[11];
    const float* ln2b = (const float*)d_in[12];
    const float* w1   = (const float*)d_in[13];
    const float* b1   = (const float*)d_in[14];
    const float* w2   = (const float*)d_in[15];
    const float* b2   = (const float*)d_in[16];
    float* out = (float*)d_out;

    float* x2;
    cudaGetSymbolAddress((void**)&x2, g_x2);

    __nv_bfloat16 *ahi, *alo, *qhi, *qlo, *khi, *klo, *vhi, *vlo, *mhi, *mlo;
    __nv_bfloat16 *wqth, *wqtl, *wkth, *wktl, *wvth, *wvtl, *woth, *wotl;
    __nv_bfloat16 *w1th, *w1tl, *w2th, *w2tl;
    cudaGetSymbolAddress((void**)&ahi,  g_ahi);
    cudaGetSymbolAddress((void**)&alo,  g_alo);
    cudaGetSymbolAddress((void**)&qhi,  g_qhi);
    cudaGetSymbolAddress((void**)&qlo,  g_qlo);
    cudaGetSymbolAddress((void**)&khi,  g_khi);
    cudaGetSymbolAddress((void**)&klo,  g_klo);
    cudaGetSymbolAddress((void**)&vhi,  g_vhi);
    cudaGetSymbolAddress((void**)&vlo,  g_vlo);
    cudaGetSymbolAddress((void**)&mhi,  g_mhi);
    cudaGetSymbolAddress((void**)&mlo,  g_mlo);
    cudaGetSymbolAddress((void**)&wqth, g_wqth);
    cudaGetSymbolAddress((void**)&wqtl, g_wqtl);
    cudaGetSymbolAddress((void**)&wkth, g_wkth);
    cudaGetSymbolAddress((void**)&wktl, g_wktl);
    cudaGetSymbolAddress((void**)&wvth, g_wvth);
    cudaGetSymbolAddress((void**)&wvtl, g_wvtl);
    cudaGetSymbolAddress((void**)&woth, g_woth);
    cudaGetSymbolAddress((void**)&wotl, g_wotl);
    cudaGetSymbolAddress((void**)&w1th, g_w1th);
    cudaGetSymbolAddress((void**)&w1tl, g_w1tl);
    cudaGetSymbolAddress((void**)&w2th, g_w2th);
    cudaGetSymbolAddress((void**)&w2tl, g_w2tl);

    cudaFuncSetAttribute(gemm_mma<0,0,1>, cudaFuncAttributeMaxDynamicSharedMemorySize, GSMEM_BYTES);
    cudaFuncSetAttribute(gemm_mma<1,0,0>, cudaFuncAttributeMaxDynamicSharedMemorySize, GSMEM_BYTES);
    cudaFuncSetAttribute(gemm_mma<0,1,1>, cudaFuncAttributeMaxDynamicSharedMemorySize, GSMEM_BYTES);
    cudaFuncSetAttribute(flash_kernel, cudaFuncAttributeMaxDynamicSharedMemorySize, FSMEM);

    dim3 tb(32, 8);

    // weight transpose+split
    transpose_split_kernel<<<dim3(DD/32,  DD/32),  tb>>>(wq, wqth, wqtl, DD,  DD);
    transpose_split_kernel<<<dim3(DD/32,  DD/32),  tb>>>(wk, wkth, wktl, DD,  DD);
    transpose_split_kernel<<<dim3(DD/32,  DD/32),  tb>>>(wv, wvth, wvtl, DD,  DD);
    transpose_split_kernel<<<dim3(DD/32,  DD/32),  tb>>>(wo, woth, wotl, DD,  DD);
    transpose_split_kernel<<<dim3(DFF/32, DD/32),  tb>>>(w1, w1th, w1tl, DD,  DFF);
    transpose_split_kernel<<<dim3(DD/32,  DFF/32), tb>>>(w2, w2th, w2tl, DFF, DD);

    // 1. h1 = LN(x) -> hi/lo
    ln_split_kernel<<<MM, 256>>>(x, ln1g, ln1b, ahi, alo);

    // 2. Q/K/V projections -> hi/lo bf16 only (Q pre-scaled by 1/8)
    dim3 g1(DD/128, MM/128);
    gemm_mma<0,0,1><<<g1, 256, GSMEM_BYTES>>>(ahi, alo, wqth, wqtl, bq, nullptr,
        nullptr, qhi, qlo, 0.125f, DD, DD);
    gemm_mma<0,0,1><<<g1, 256, GSMEM_BYTES>>>(ahi, alo, wkth, wktl, bk, nullptr,
        nullptr, khi, klo, 1.0f, DD, DD);
    gemm_mma<0,0,1><<<g1, 256, GSMEM_BYTES>>>(ahi, alo, wvth, wvtl, bv, nullptr,
        nullptr, vhi, vlo, 1.0f, DD, DD);

    // 3. fused flash attention -> ctx hi/lo (reuse ahi/alo)
    flash_kernel<<<dim3(SS/128, BB*HH), 256, FSMEM>>>(
        qhi, qlo, khi, klo, vhi, vlo, ahi, alo);

    // 4. x2 = x + ctx @ wo + bo  (fp32 out)
    gemm_mma<1,0,0><<<g1, 256, GSMEM_BYTES>>>(ahi, alo, woth, wotl, bo, x,
        x2, nullptr, nullptr, 1.0f, DD, DD);

    // 5. h2 = LN(x2) -> hi/lo (reuse qhi/qlo)
    ln_split_kernel<<<MM, 256>>>(x2, ln2g, ln2b, qhi, qlo);

    // 6. mlp = gelu(h2 @ w1 + b1) -> hi/lo
    dim3 g2(DFF/128, MM/128);
    gemm_mma<0,1,1><<<g2, 256, GSMEM_BYTES>>>(qhi, qlo, w1th, w1tl, b1, nullptr,
        nullptr, mhi, mlo, 1.0f, DFF, DD);

    // 7. out = x2 + mlp @ w2 + b2
    gemm_mma<1,0,0><<<g1, 256, GSMEM_BYTES>>>(mhi, mlo, w2th, w2tl, b2, x2,
        out, nullptr, nullptr, 1.0f, DD, DFF);
}

// round 10
// speedup vs baseline: 3.1533x; 1.0919x over previous
#include <cuda_runtime.h>
#include <cuda_bf16.h>
#include <math.h>
#include <stdint.h>

#define BB  4
#define SS  1024
#define DD  1024
#define HH  16
#define HDm 64
#define MM  (BB*SS)      // 4096
#define DFF (4*DD)       // 4096
#define LNEPS 1e-5f

// ---------------- scratch ----------------------------------------------------
__device__ float g_x2 [(size_t)MM*DD];
__device__ float g_bqkv[3*DD];

// bf16 hi/lo buffers (uint4 => 16B aligned)
__device__ uint4 g_ahi [(size_t)MM*DD*2/16];   // h1 -> later ctx
__device__ uint4 g_alo [(size_t)MM*DD*2/16];
__device__ uint4 g_qhi [(size_t)MM*DD*2/16];   // q -> later h2
__device__ uint4 g_qlo [(size_t)MM*DD*2/16];
__device__ uint4 g_khi [(size_t)MM*DD*2/16];
__device__ uint4 g_klo [(size_t)MM*DD*2/16];
__device__ uint4 g_vhi [(size_t)MM*DD*2/16];
__device__ uint4 g_vlo [(size_t)MM*DD*2/16];
__device__ uint4 g_mhi [(size_t)MM*DFF*2/16];
__device__ uint4 g_mlo [(size_t)MM*DFF*2/16];
__device__ uint4 g_wqkvth[(size_t)3*DD*DD*2/16];
__device__ uint4 g_wqkvtl[(size_t)3*DD*DD*2/16];
__device__ uint4 g_woth[(size_t)DD*DD*2/16];
__device__ uint4 g_wotl[(size_t)DD*DD*2/16];
__device__ uint4 g_w1th[(size_t)DD*DFF*2/16];
__device__ uint4 g_w1tl[(size_t)DD*DFF*2/16];
__device__ uint4 g_w2th[(size_t)DFF*DD*2/16];
__device__ uint4 g_w2tl[(size_t)DFF*DD*2/16];

// ---------------- PTX helpers (sm_80+ baseline) ------------------------------
__device__ __forceinline__ uint32_t smem_to_u32(const void* p) {
    uint32_t a;
    asm("{ .reg .u64 t; cvta.to.shared.u64 t, %1; cvt.u32.u64 %0, t; }" : "=r"(a) : "l"(p));
    return a;
}
__device__ __forceinline__ void cp16(uint32_t dst, const void* src) {
    asm volatile("cp.async.cg.shared.global [%0], [%1], 16;" :: "r"(dst), "l"(src) : "memory");
}
__device__ __forceinline__ void ldsm4(uint32_t* r, uint32_t a) {
    asm volatile("ldmatrix.sync.aligned.m8n8.x4.shared.b16 {%0,%1,%2,%3}, [%4];"
        : "=r"(r[0]), "=r"(r[1]), "=r"(r[2]), "=r"(r[3]) : "r"(a));
}
__device__ __forceinline__ void ldsm4t(uint32_t* r, uint32_t a) {
    asm volatile("ldmatrix.sync.aligned.m8n8.x4.trans.shared.b16 {%0,%1,%2,%3}, [%4];"
        : "=r"(r[0]), "=r"(r[1]), "=r"(r[2]), "=r"(r[3]) : "r"(a));
}
__device__ __forceinline__ void mma16816(float* d, const uint32_t* a, const uint32_t* b) {
    asm volatile("mma.sync.aligned.m16n8k16.row.col.f32.bf16.bf16.f32 "
        "{%0,%1,%2,%3}, {%4,%5,%6,%7}, {%8,%9}, {%0,%1,%2,%3};"
        : "+f"(d[0]), "+f"(d[1]), "+f"(d[2]), "+f"(d[3])
        : "r"(a[0]), "r"(a[1]), "r"(a[2]), "r"(a[3]), "r"(b[0]), "r"(b[1]));
}
__device__ __forceinline__ void packhl(float x, float y, uint32_t& hi, uint32_t& lo) {
    __nv_bfloat16 hx = __float2bfloat16_rn(x), hy = __float2bfloat16_rn(y);
    __nv_bfloat16 lx = __float2bfloat16_rn(x - __bfloat162float(hx));
    __nv_bfloat16 ly = __float2bfloat16_rn(y - __bfloat162float(hy));
    __nv_bfloat162 h2 = __halves2bfloat162(hx, hy), l2 = __halves2bfloat162(lx, ly);
    hi = *(uint32_t*)&h2; lo = *(uint32_t*)&l2;
}

// ---------------- LayerNorm with vectorized hi/lo split output ---------------
__global__ __launch_bounds__(256) void ln_split_kernel(
    const float* __restrict__ x, const float* __restrict__ g,
    const float* __restrict__ b,
    __nv_bfloat16* __restrict__ ohi, __nv_bfloat16* __restrict__ olo)
{
    int row = blockIdx.x;
    int t = threadIdx.x;
    const float* xr = x + (size_t)row * DD;
    float4 v = *(const float4*)(xr + 4*t);
    float s = v.x + v.y + v.z + v.w;

    __shared__ float warpsum[8];
    __shared__ float s_mean, s_inv;
    int lane = t & 31, wid = t >> 5;
#pragma unroll
    for (int o = 16; o > 0; o >>= 1) s += __shfl_xor_sync(~0u, s, o);
    if (lane == 0) warpsum[wid] = s;
    __syncthreads();
    if (t == 0) {
        float tot = 0.f;
#pragma unroll
        for (int i = 0; i < 8; i++) tot += warpsum[i];
        s_mean = tot * (1.f/DD);
    }
    __syncthreads();
    float mean = s_mean;
    float d0 = v.x-mean, d1 = v.y-mean, d2 = v.z-mean, d3 = v.w-mean;
    float ss = d0*d0 + d1*d1 + d2*d2 + d3*d3;
#pragma unroll
    for (int o = 16; o > 0; o >>= 1) ss += __shfl_xor_sync(~0u, ss, o);
    if (lane == 0) warpsum[wid] = ss;
    __syncthreads();
    if (t == 0) {
        float tot = 0.f;
#pragma unroll
        for (int i = 0; i < 8; i++) tot += warpsum[i];
        s_inv = rsqrtf(tot * (1.f/DD) + LNEPS);
    }
    __syncthreads();
    float inv = s_inv;

    float4 gv = *(const float4*)(g + 4*t);
    float4 bv = *(const float4*)(b + 4*t);
    float o0 = d0 * inv * gv.x + bv.x;
    float o1 = d1 * inv * gv.y + bv.y;
    float o2 = d2 * inv * gv.z + bv.z;
    float o3 = d3 * inv * gv.w + bv.w;
    uint32_t h01, l01, h23, l23;
    packhl(o0, o1, h01, l01);
    packhl(o2, o3, h23, l23);
    uint2 hv; hv.x = h01; hv.y = h23;
    uint2 lv; lv.x = l01; lv.y = l23;
    *(uint2*)(ohi + (size_t)row*DD + 4*t) = hv;
    *(uint2*)(olo + (size_t)row*DD + 4*t) = lv;
}

// ---------------- bias concat -------------------------------------------------
__global__ void concat3_kernel(const float* __restrict__ a, const float* __restrict__ b,
                               const float* __restrict__ c, float* __restrict__ o)
{
    int i = blockIdx.x * 256 + threadIdx.x;
    if (i < DD) o[i] = a[i];
    else if (i < 2*DD) o[i] = b[i - DD];
    else o[i] = c[i - 2*DD];
}

// ---------------- weight transpose+split: W[K][N] -> Wt_hi/lo [N][K] ---------
__global__ __launch_bounds__(256) void transpose_split_kernel(
    const float* __restrict__ W, __nv_bfloat16* __restrict__ Thi,
    __nv_bfloat16* __restrict__ Tlo, int K, int N)
{
    __shared__ float tile[32][33];
    int n0 = blockIdx.x * 32, k0 = blockIdx.y * 32;
    int tx = threadIdx.x, ty = threadIdx.y;  // 32 x 8
#pragma unroll
    for (int r = 0; r < 4; r++)
        tile[ty + 8*r][tx] = W[(size_t)(k0 + ty + 8*r) * N + n0 + tx];
    __syncthreads();
#pragma unroll
    for (int r = 0; r < 4; r++) {
        int rr = ty + 8*r;
        float v = tile[tx][rr];
        __nv_bfloat16 h = __float2bfloat16_rn(v);
        __nv_bfloat16 l = __float2bfloat16_rn(v - __bfloat162float(h));
        size_t oi = (size_t)(n0 + rr) * K + k0 + tx;
        Thi[oi] = h; Tlo[oi] = l;
    }
}

// ---------------- warp-MMA split-bf16 GEMM -----------------------------------
// C = A @ B^T : A [M,K] hi/lo, B [N,K] hi/lo. 128x128 CTA tile, 8 warps 64x32.
// 3-stage cp.async pipeline; one __syncthreads per K-chunk.
// MODE: 0 = fp32 out + residual; 2 = gelu + split hi/lo out; 3 = fused QKV route
#define SUBB   (128*144)
#define STAGEB (4*SUBB)              // 73728 B
#define GSMEM_BYTES (3*STAGEB)       // 221184 B

__device__ __forceinline__ void ld_chunk(uint32_t s0, int tid,
    const char* a0, const char* a1, const char* b0, const char* b1,
    size_t strb, int kc)
{
    const char* bases[4] = { a0, a1, b0, b1 };
#pragma unroll
    for (int mtx = 0; mtx < 4; mtx++) {
        const char* base = bases[mtx];
#pragma unroll
        for (int t = 0; t < 4; t++) {
            int seg = t*256 + tid;
            int r = seg >> 3, s = seg & 7;
            cp16(s0 + mtx*SUBB + r*144 + s*16,
                 base + (size_t)r * strb + (size_t)kc * 128 + s*16);
        }
    }
    asm volatile("cp.async.commit_group;" ::: "memory");
}

template<int MODE>
__global__ __launch_bounds__(256) void gemm_mma(
    const __nv_bfloat16* __restrict__ Ahi, const __nv_bfloat16* __restrict__ Alo,
    const __nv_bfloat16* __restrict__ Bhi, const __nv_bfloat16* __restrict__ Blo,
    const float* __restrict__ bias, const float* __restrict__ res,
    float* __restrict__ C,
    __nv_bfloat16* __restrict__ O0h, __nv_bfloat16* __restrict__ O0l,
    __nv_bfloat16* __restrict__ O1h, __nv_bfloat16* __restrict__ O1l,
    __nv_bfloat16* __restrict__ O2h, __nv_bfloat16* __restrict__ O2l,
    int N, int K)
{
    extern __shared__ char smem[];
    uint32_t sb = smem_to_u32(smem);
    int tid = threadIdx.x, lane = tid & 31, wid = tid >> 5;
    int m0 = blockIdx.y * 128, n0 = blockIdx.x * 128;
    int wr = wid >> 2, wc = wid & 3;

    size_t strb = (size_t)K * 2;
    const char* a0 = (const char*)(Ahi + (size_t)m0 * K);
    const char* a1 = (const char*)(Alo + (size_t)m0 * K);
    const char* b0 = (const char*)(Bhi + (size_t)n0 * K);
    const char* b1 = (const char*)(Blo + (size_t)n0 * K);

    float acc[4][4][4];
#pragma unroll
    for (int i = 0; i < 4; i++)
#pragma unroll
        for (int j = 0; j < 4; j++)
#pragma unroll
            for (int r = 0; r < 4; r++) acc[i][j][r] = 0.f;

    int NC = K >> 6;
    ld_chunk(sb, tid, a0, a1, b0, b1, strb, 0);
    if (NC > 1) ld_chunk(sb + STAGEB, tid, a0, a1, b0, b1, strb, 1);

    int cs = 0, ns = 2;
    for (int i = 0; i < NC; i++) {
        if (i + 1 < NC) { asm volatile("cp.async.wait_group 1;" ::: "memory"); }
        else            { asm volatile("cp.async.wait_group 0;" ::: "memory"); }
        __syncthreads();

        uint32_t st = sb + cs*STAGEB;
        uint32_t a_base = st + (wr*64 + (lane & 15))*144 + (lane >> 4)*16;
        uint32_t b_base = st + 2*SUBB +
            (wc*32 + (lane & 7) + ((lane >> 4) & 1)*8)*144 + ((lane >> 3) & 1)*16;

#pragma unroll
        for (int ks = 0; ks < 4; ks++) {
            uint32_t ah[4][4], al[4][4], bh[2][4], bl[2][4];
#pragma unroll
            for (int mi = 0; mi < 4; mi++) {
                uint32_t ad = a_base + mi*16*144 + ks*32;
                ldsm4(ah[mi], ad);
                ldsm4(al[mi], ad + SUBB);
            }
#pragma unroll
            for (int bj = 0; bj < 2; bj++) {
                uint32_t bd = b_base + bj*16*144 + ks*32;
                ldsm4(bh[bj], bd);
                ldsm4(bl[bj], bd + SUBB);
            }
#pragma unroll
            for (int mi = 0; mi < 4; mi++) {
#pragma unroll
                for (int nj = 0; nj < 4; nj++) {
                    const uint32_t* bH = &bh[nj >> 1][(nj & 1)*2];
                    const uint32_t* bL = &bl[nj >> 1][(nj & 1)*2];
                    mma16816(acc[mi][nj], ah[mi], bH);
                    mma16816(acc[mi][nj], ah[mi], bL);
                    mma16816(acc[mi][nj], al[mi], bH);
                }
            }
        }

        if (i + 2 < NC)
            ld_chunk(sb + ns*STAGEB, tid, a0, a1, b0, b1, strb, i + 2);
        cs = (cs + 1 == 3) ? 0 : cs + 1;
        ns = (ns + 1 == 3) ? 0 : ns + 1;
    }

    // ---- epilogue ----
    // QKV routing: the 128-col tile never crosses a 1024 boundary.
    const __nv_bfloat16* dummy = nullptr; (void)dummy;
    __nv_bfloat16 *oh = O0h, *ol = O0l;
    int lc0 = n0;
    float scale = 1.0f;
    if (MODE == 3) {
        int mat = n0 >> 10;
        lc0 = n0 & 1023;
        oh = (mat == 0) ? O0h : ((mat == 1) ? O1h : O2h);
        ol = (mat == 0) ? O0l : ((mat == 1) ? O1l : O2l);
        scale = (mat == 0) ? 0.125f : 1.0f;
    }

    float bx[4], by[4];
#pragma unroll
    for (int nj = 0; nj < 4; nj++) {
        int c = n0 + wc*32 + nj*8 + (lane & 3)*2;
        bx[nj] = bias[c]; by[nj] = bias[c+1];
    }
#pragma unroll
    for (int mi = 0; mi < 4; mi++) {
        int rbase = m0 + wr*64 + mi*16 + (lane >> 2);
#pragma unroll
        for (int half = 0; half < 2; half++) {
            int r = rbase + half*8;
#pragma unroll
            for (int nj = 0; nj < 4; nj++) {
                int cc = wc*32 + nj*8 + (lane & 3)*2;
                float v0 = acc[mi][nj][half*2+0] + bx[nj];
                float v1 = acc[mi][nj][half*2+1] + by[nj];
                if (MODE == 2) {
                    v0 = 0.5f * v0 * (1.f + erff(v0 * 0.70710678118654752f));
                    v1 = 0.5f * v1 * (1.f + erff(v1 * 0.70710678118654752f));
                }
                if (MODE == 0) {
                    int c = n0 + cc;
                    float2 rv = *(const float2*)(res + (size_t)r * N + c);
                    float2 o; o.x = v0 + rv.x; o.y = v1 + rv.y;
                    *(float2*)(C + (size_t)r * N + c) = o;
                } else if (MODE == 2) {
                    uint32_t hi, lo;
                    packhl(v0, v1, hi, lo);
                    int c = n0 + cc;
                    *(uint32_t*)(oh + (size_t)r * N + c) = hi;
                    *(uint32_t*)(ol + (size_t)r * N + c) = lo;
                } else { // MODE 3
                    v0 *= scale; v1 *= scale;
                    uint32_t hi, lo;
                    packhl(v0, v1, hi, lo);
                    int c = lc0 + cc;
                    *(uint32_t*)(oh + (size_t)r * DD + c) = hi;
                    *(uint32_t*)(ol + (size_t)r * DD + c) = lo;
                }
            }
        }
    }
}

// ---------------- fused flash attention --------------------------------------
// grid (SS/128, BB*HH), 256 threads (8 warps x 16 q-rows).
#define FQH 0
#define FQL 18432
#define FKH 36864
#define FKL 55296
#define FVH 73728
#define FVL 92160
#define FSMEM 110592

__device__ __forceinline__ void fl_load_tile(uint32_t dst, int tid, const char* g)
{
#pragma unroll
    for (int t = 0; t < 4; t++) {
        int seg = t*256 + tid;
        int r = seg >> 3, s = seg & 7;
        cp16(dst + r*144 + s*16, g + (size_t)r * (DD*2) + s*16);
    }
}

__global__ __launch_bounds__(256) void flash_kernel(
    const __nv_bfloat16* __restrict__ qhi, const __nv_bfloat16* __restrict__ qlo,
    const __nv_bfloat16* __restrict__ khi, const __nv_bfloat16* __restrict__ klo,
    const __nv_bfloat16* __restrict__ vhi, const __nv_bfloat16* __restrict__ vlo,
    __nv_bfloat16* __restrict__ chi, __nv_bfloat16* __restrict__ clo)
{
    extern __shared__ char smem[];
    uint32_t sb = smem_to_u32(smem);
    int tid = threadIdx.x, lane = tid & 31, w = tid >> 5;
    int q0 = blockIdx.x * 128;
    int bh = blockIdx.y, b = bh >> 4, h = bh & 15;

    size_t qoff = ((size_t)(b*SS + q0) * DD + h*HDm) * 2;
    size_t koff = ((size_t)(b*SS) * DD + h*HDm) * 2;

    fl_load_tile(sb + FQH, tid, (const char*)qhi + qoff);
    fl_load_tile(sb + FQL, tid, (const char*)qlo + qoff);
    fl_load_tile(sb + FKH, tid, (const char*)khi + koff);
    fl_load_tile(sb + FKL, tid, (const char*)klo + koff);
    fl_load_tile(sb + FVH, tid, (const char*)vhi + koff);
    fl_load_tile(sb + FVL, tid, (const char*)vlo + koff);
    asm volatile("cp.async.commit_group;" ::: "memory");

    float oacc[8][4];
#pragma unroll
    for (int i = 0; i < 8; i++)
#pragma unroll
        for (int r = 0; r < 4; r++) oacc[i][r] = 0.f;
    float mrow[2] = { -1e30f, -1e30f };
    float lrow[2] = { 0.f, 0.f };

    uint32_t a_base = sb + FQH + (w*16 + (lane & 15))*144 + (lane >> 4)*16;

    for (int j = 0; j < SS/128; j++) {
        asm volatile("cp.async.wait_group 0;" ::: "memory");
        __syncthreads();

        float sacc[16][4];
#pragma unroll
        for (int i = 0; i < 16; i++)
#pragma unroll
            for (int r = 0; r < 4; r++) sacc[i][r] = 0.f;

#pragma unroll
        for (int ks = 0; ks < 4; ks++) {
            uint32_t ah[4], al[4];
            ldsm4(ah, a_base + ks*32);
            ldsm4(al, a_base + (FQL-FQH) + ks*32);
#pragma unroll
            for (int nt = 0; nt < 8; nt++) {
                uint32_t bh4[4], bl4[4];
                uint32_t bd = sb + FKH + (nt*16 + (lane & 7) + ((lane >> 4) & 1)*8)*144
                            + ((lane >> 3) & 1)*16 + ks*32;
                ldsm4(bh4, bd);
                ldsm4(bl4, bd + (FKL-FKH));
#pragma unroll
                for (int half = 0; half < 2; half++) {
                    mma16816(sacc[2*nt+half], ah, &bh4[half*2]);
                    mma16816(sacc[2*nt+half], ah, &bl4[half*2]);
                    mma16816(sacc[2*nt+half], al, &bh4[half*2]);
                }
            }
        }

#pragma unroll
        for (int half = 0; half < 2; half++) {
            float mx = -1e30f;
#pragma unroll
            for (int nt = 0; nt < 16; nt++) {
                mx = fmaxf(mx, sacc[nt][half*2+0]);
                mx = fmaxf(mx, sacc[nt][half*2+1]);
            }
            mx = fmaxf(mx, __shfl_xor_sync(~0u, mx, 1));
            mx = fmaxf(mx, __shfl_xor_sync(~0u, mx, 2));
            float mnew = fmaxf(mrow[half], mx);
            float alpha = __expf(mrow[half] - mnew);
            mrow[half] = mnew;
            float sum = 0.f;
#pragma unroll
            for (int nt = 0; nt < 16; nt++) {
                float p0 = __expf(sacc[nt][half*2+0] - mnew);
                float p1 = __expf(sacc[nt][half*2+1] - mnew);
                sacc[nt][half*2+0] = p0; sacc[nt][half*2+1] = p1;
                sum += p0 + p1;
            }
            lrow[half] = lrow[half] * alpha + sum;
#pragma unroll
            for (int on = 0; on < 8; on++) {
                oacc[on][half*2+0] *= alpha;
                oacc[on][half*2+1] *= alpha;
            }
        }

#pragma unroll
        for (int kt = 0; kt < 8; kt++) {
            uint32_t phi[4], plo[4];
            packhl(sacc[2*kt  ][0], sacc[2*kt  ][1], phi[0], plo[0]);
            packhl(sacc[2*kt  ][2], sacc[2*kt  ][3], phi[1], plo[1]);
            packhl(sacc[2*kt+1][0], sacc[2*kt+1][1], phi[2], plo[2]);
            packhl(sacc[2*kt+1][2], sacc[2*kt+1][3], phi[3], plo[3]);
#pragma unroll
            for (int np = 0; np < 4; np++) {
                uint32_t vh4[4], vl4[4];
                uint32_t vd = sb + FVH + (16*kt + (lane & 15))*144
                            + (np*16 + (lane >> 4)*8)*2;
                ldsm4t(vh4, vd);
                ldsm4t(vl4, vd + (FVL-FVH));
#pragma unroll
                for (int half = 0; half < 2; half++) {
                    mma16816(oacc[2*np+half], phi, &vh4[half*2]);
                    mma16816(oacc[2*np+half], phi, &vl4[half*2]);
                    mma16816(oacc[2*np+half], plo, &vh4[half*2]);
                }
            }
        }

        __syncthreads();
        if (j + 1 < SS/128) {
            size_t off = koff + (size_t)(j+1) * 128 * DD * 2;
            fl_load_tile(sb + FKH, tid, (const char*)khi + off);
            fl_load_tile(sb + FKL, tid, (const char*)klo + off);
            fl_load_tile(sb + FVH, tid, (const char*)vhi + off);
            fl_load_tile(sb + FVL, tid, (const char*)vlo + off);
            asm volatile("cp.async.commit_group;" ::: "memory");
        }
    }

#pragma unroll
    for (int half = 0; half < 2; half++) {
        float l = lrow[half];
        l += __shfl_xor_sync(~0u, l, 1);
        l += __shfl_xor_sync(~0u, l, 2);
        float inv = 1.f / l;
        int r = b*SS + q0 + w*16 + (lane >> 2) + half*8;
#pragma unroll
        for (int on = 0; on < 8; on++) {
            int c = h*HDm + on*8 + (lane & 3)*2;
            float v0 = oacc[on][half*2+0] * inv;
            float v1 = oacc[on][half*2+1] * inv;
            uint32_t hi, lo;
            packhl(v0, v1, hi, lo);
            *(uint32_t*)(chi + (size_t)r * DD + c) = hi;
            *(uint32_t*)(clo + (size_t)r * DD + c) = lo;
        }
    }
}

// ---------------- launch ------------------------------------------------------
extern "C" void kernel_launch(void* const* d_in, const int* in_sizes, int n_in,
                              void* d_out, int out_size)
{
    const float* x    = (const float*)d_in[0];
    const float* ln1g = (const float*)d_in[1];
    const float* ln1b = (const float*)d_in[2];
    const float* wq   = (const float*)d_in[3];
    const float* bq   = (const float*)d_in[4];
    const float* wk   = (const float*)d_in[5];
    const float* bk   = (const float*)d_in[6];
    const float* wv   = (const float*)d_in[7];
    const float* bv   = (const float*)d_in[8];
    const float* wo   = (const float*)d_in[9];
    const float* bo   = (const float*)d_in[10];
    const float* ln2g = (const float*)d_in[11];
    const float* ln2b = (const float*)d_in[12];
    const float* w1   = (const float*)d_in[13];
    const float* b1   = (const float*)d_in[14];
    const float* w2   = (const float*)d_in[15];
    const float* b2   = (const float*)d_in[16];
    float* out = (float*)d_out;

    float *x2, *bqkv;
    cudaGetSymbolAddress((void**)&x2, g_x2);
    cudaGetSymbolAddress((void**)&bqkv, g_bqkv);

    __nv_bfloat16 *ahi, *alo, *qhi, *qlo, *khi, *klo, *vhi, *vlo, *mhi, *mlo;
    __nv_bfloat16 *wqkvth, *wqkvtl, *woth, *wotl, *w1th, *w1tl, *w2th, *w2tl;
    cudaGetSymbolAddress((void**)&ahi,  g_ahi);
    cudaGetSymbolAddress((void**)&alo,  g_alo);
    cudaGetSymbolAddress((void**)&qhi,  g_qhi);
    cudaGetSymbolAddress((void**)&qlo,  g_qlo);
    cudaGetSymbolAddress((void**)&khi,  g_khi);
    cudaGetSymbolAddress((void**)&klo,  g_klo);
    cudaGetSymbolAddress((void**)&vhi,  g_vhi);
    cudaGetSymbolAddress((void**)&vlo,  g_vlo);
    cudaGetSymbolAddress((void**)&mhi,  g_mhi);
    cudaGetSymbolAddress((void**)&mlo,  g_mlo);
    cudaGetSymbolAddress((void**)&wqkvth, g_wqkvth);
    cudaGetSymbolAddress((void**)&wqkvtl, g_wqkvtl);
    cudaGetSymbolAddress((void**)&woth, g_woth);
    cudaGetSymbolAddress((void**)&wotl, g_wotl);
    cudaGetSymbolAddress((void**)&w1th, g_w1th);
    cudaGetSymbolAddress((void**)&w1tl, g_w1tl);
    cudaGetSymbolAddress((void**)&w2th, g_w2th);
    cudaGetSymbolAddress((void**)&w2tl, g_w2tl);

    cudaFuncSetAttribute(gemm_mma<0>, cudaFuncAttributeMaxDynamicSharedMemorySize, GSMEM_BYTES);
    cudaFuncSetAttribute(gemm_mma<2>, cudaFuncAttributeMaxDynamicSharedMemorySize, GSMEM_BYTES);
    cudaFuncSetAttribute(gemm_mma<3>, cudaFuncAttributeMaxDynamicSharedMemorySize, GSMEM_BYTES);
    cudaFuncSetAttribute(flash_kernel, cudaFuncAttributeMaxDynamicSharedMemorySize, FSMEM);

    dim3 tb(32, 8);

    // weight transpose+split (QKV concatenated into one [3072][1024] buffer)
    transpose_split_kernel<<<dim3(DD/32,  DD/32),  tb>>>(wq, wqkvth,            wqkvtl,            DD,  DD);
    transpose_split_kernel<<<dim3(DD/32,  DD/32),  tb>>>(wk, wqkvth + (size_t)DD*DD,   wqkvtl + (size_t)DD*DD,   DD,  DD);
    transpose_split_kernel<<<dim3(DD/32,  DD/32),  tb>>>(wv, wqkvth + (size_t)2*DD*DD, wqkvtl + (size_t)2*DD*DD, DD,  DD);
    transpose_split_kernel<<<dim3(DD/32,  DD/32),  tb>>>(wo, woth, wotl, DD,  DD);
    transpose_split_kernel<<<dim3(DFF/32, DD/32),  tb>>>(w1, w1th, w1tl, DD,  DFF);
    transpose_split_kernel<<<dim3(DD/32,  DFF/32), tb>>>(w2, w2th, w2tl, DFF, DD);
    concat3_kernel<<<12, 256>>>(bq, bk, bv, bqkv);

    // 1. h1 = LN(x) -> hi/lo
    ln_split_kernel<<<MM, 256>>>(x, ln1g, ln1b, ahi, alo);

    // 2. fused QKV projection -> q/k/v hi/lo (Q pre-scaled by 1/8)
    dim3 gqkv(3*DD/128, MM/128);
    gemm_mma<3><<<gqkv, 256, GSMEM_BYTES>>>(ahi, alo, wqkvth, wqkvtl, bqkv, nullptr,
        nullptr, qhi, qlo, khi, klo, vhi, vlo, 3*DD, DD);

    // 3. fused flash attention -> ctx hi/lo (reuse ahi/alo)
    flash_kernel<<<dim3(SS/128, BB*HH), 256, FSMEM>>>(
        qhi, qlo, khi, klo, vhi, vlo, ahi, alo);

    // 4. x2 = x + ctx @ wo + bo  (fp32 out)
    dim3 g1(DD/128, MM/128);
    gemm_mma<0><<<g1, 256, GSMEM_BYTES>>>(ahi, alo, woth, wotl, bo, x,
        x2, nullptr, nullptr, nullptr, nullptr, nullptr, nullptr, DD, DD);

    // 5. h2 = LN(x2) -> hi/lo (reuse qhi/qlo)
    ln_split_kernel<<<MM, 256>>>(x2, ln2g, ln2b, qhi, qlo);

    // 6. mlp = gelu(h2 @ w1 + b1) -> hi/lo
    dim3 g2(DFF/128, MM/128);
    gemm_mma<2><<<g2, 256, GSMEM_BYTES>>>(qhi, qlo, w1th, w1tl, b1, nullptr,
        nullptr, mhi, mlo, nullptr, nullptr, nullptr, nullptr, DFF, DD);

    // 7. out = x2 + mlp @ w2 + b2
    gemm_mma<0><<<g1, 256, GSMEM_BYTES>>>(mhi, mlo, w2th, w2tl, b2, x2,
        out, nullptr, nullptr, nullptr, nullptr, nullptr, nullptr, DD, DFF);
}